// round 2
// baseline (speedup 1.0000x reference)
#include <cuda_runtime.h>
#include <cuda_bf16.h>
#include <math.h>

#define Bn 16
#define Nn 2048
#define Fn 64
#define Tn 32
#define CHUNKS 64              // chunks per batch
#define NC (Nn / CHUNKS)       // 32 nodes per chunk
#define NBLK (Bn * CHUNKS)     // 1024 reduce blocks

// Partial accumulators: [block][0=lhs1,1=R2][f*t]  (16 MB)
__device__ float g_partial[NBLK][2][Fn * Tn];
// Per-batch reduced sums: [b][0=lhs1,1=R2][f*t]  (512 KB)
__device__ float g_sum[Bn][2 * Fn * Tn];

__device__ __forceinline__ float4 f4zero() { return make_float4(0.f, 0.f, 0.f, 0.f); }
__device__ __forceinline__ void f4fma(float4& a, float s, const float4& v) {
    a.x = fmaf(s, v.x, a.x); a.y = fmaf(s, v.y, a.y);
    a.z = fmaf(s, v.z, a.z); a.w = fmaf(s, v.w, a.w);
}
__device__ __forceinline__ void f4add(float4& a, const float4& v) {
    a.x += v.x; a.y += v.y; a.z += v.z; a.w += v.w;
}

// ---------------------------------------------------------------------------
// Pass 1: stream x once (256 MB).
//   lhs1[f][t] += U1[n] * x[b,n,f,t]
//   r[t]       = sum_f U3[f] * x[b,n,f,t]
//   R2[f][t]   += U2[f,n] * r[t]
// Mapping: q = tid&7 owns t-quad [4q,4q+4); fr = tid>>3 owns f rows {fr, fr+32}.
// Each warp load instruction moves 512 B (4 rows x 128 B), fully coalesced.
// Cross-f reduction of r: 2 warp shuffles + staged shared write, barrier only
// once per 8-node group (8 barriers/block total).
// ---------------------------------------------------------------------------
__global__ __launch_bounds__(256, 4)
void reduce_kernel(const float* __restrict__ x,
                   const float* __restrict__ U1,
                   const float* __restrict__ U2,
                   const float* __restrict__ U3)
{
    const int blk  = blockIdx.x;       // 0..NBLK-1
    const int b    = blk / CHUNKS;
    const int c    = blk % CHUNKS;
    const int n0   = c * NC;
    const int tid  = threadIdx.x;
    const int q    = tid & 7;          // t-quad index (t = 4q..4q+3)
    const int fr   = tid >> 3;         // f row 0..31 (also owns fr+32)
    const int w    = tid >> 5;         // warp 0..7
    const int lane = tid & 31;

    __shared__ float  U2s[NC][Fn + 1]; // U2s[nn][f] = U2[f*N + n0+nn]
    __shared__ float  U3s[Fn];
    __shared__ float  U1s[NC];
    __shared__ float4 red[8][8][8];    // [node-in-group][warp][q]

    if (tid < Fn) U3s[tid] = U3[tid];
    if (tid < NC) U1s[tid] = U1[n0 + tid];
    for (int i = tid; i < NC * Fn; i += 256) {
        int f  = i >> 5;
        int nn = i & 31;
        U2s[nn][f] = U2[f * Nn + n0 + nn];
    }
    __syncthreads();

    float4 accL0 = f4zero(), accL1 = f4zero();
    float4 accR0 = f4zero(), accR1 = f4zero();

    const float u3a = U3s[fr];
    const float u3b = U3s[fr + 32];
    const float* xb = x + ((size_t)b * Nn + n0) * (Fn * Tn);

    for (int g = 0; g < 4; g++) {
#pragma unroll
        for (int k = 0; k < 8; k++) {
            const int nn = g * 8 + k;
            const float* xn = xb + (size_t)nn * (Fn * Tn);
            float4 v0 = *(const float4*)(xn + fr * Tn + 4 * q);
            float4 v1 = *(const float4*)(xn + (fr + 32) * Tn + 4 * q);

            const float u1n = U1s[nn];
            f4fma(accL0, u1n, v0);
            f4fma(accL1, u1n, v1);

            float4 rp;
            rp.x = fmaf(u3a, v0.x, u3b * v1.x);
            rp.y = fmaf(u3a, v0.y, u3b * v1.y);
            rp.z = fmaf(u3a, v0.z, u3b * v1.z);
            rp.w = fmaf(u3a, v0.w, u3b * v1.w);
            // reduce over the warp's 4 fr values (lanes differing in bits 3,4)
            rp.x += __shfl_xor_sync(0xffffffffu, rp.x, 8);
            rp.y += __shfl_xor_sync(0xffffffffu, rp.y, 8);
            rp.z += __shfl_xor_sync(0xffffffffu, rp.z, 8);
            rp.w += __shfl_xor_sync(0xffffffffu, rp.w, 8);
            rp.x += __shfl_xor_sync(0xffffffffu, rp.x, 16);
            rp.y += __shfl_xor_sync(0xffffffffu, rp.y, 16);
            rp.z += __shfl_xor_sync(0xffffffffu, rp.z, 16);
            rp.w += __shfl_xor_sync(0xffffffffu, rp.w, 16);
            if (lane < 8) red[k][w][lane] = rp;   // warp-partial of r for t-quad
        }
        __syncthreads();
#pragma unroll
        for (int k = 0; k < 8; k++) {
            const int nn = g * 8 + k;
            float4 rt = red[k][0][q];
#pragma unroll
            for (int w2 = 1; w2 < 8; w2++) f4add(rt, red[k][w2][q]);
            f4fma(accR0, U2s[nn][fr],      rt);
            f4fma(accR1, U2s[nn][fr + 32], rt);
        }
        __syncthreads();
    }

    float* pl = &g_partial[blk][0][0];
    float* pr = &g_partial[blk][1][0];
    *(float4*)(pl + fr * Tn + 4 * q)        = accL0;
    *(float4*)(pl + (fr + 32) * Tn + 4 * q) = accL1;
    *(float4*)(pr + fr * Tn + 4 * q)        = accR0;
    *(float4*)(pr + (fr + 32) * Tn + 4 * q) = accR1;
}

// ---------------------------------------------------------------------------
// Pass 1.5: sum the 64 chunk partials per batch with full-grid parallelism.
// 65536 outputs, one thread each; reads 16 MB (mostly L2-resident).
// ---------------------------------------------------------------------------
__global__ __launch_bounds__(256)
void sum_partials()
{
    const int idx = blockIdx.x * 256 + threadIdx.x;  // 0..65535
    const int b = idx >> 12;                          // /4096
    const int i = idx & 4095;
    const float* p = &g_partial[b * CHUNKS][0][0] + i;
    float s = 0.f;
#pragma unroll 8
    for (int c = 0; c < CHUNKS; c++)
        s += p[(size_t)c * (2 * Fn * Tn)];
    g_sum[b][i] = s;
}

// ---------------------------------------------------------------------------
// Pass 2: per-batch epilogue (grid = B, 1024 threads). Tiny.
// ---------------------------------------------------------------------------
__global__ __launch_bounds__(1024, 1)
void epilogue_kernel(const float* __restrict__ b_e,
                     const float* __restrict__ V_e,
                     float* __restrict__ out)
{
    const int b   = blockIdx.x;
    const int tid = threadIdx.x;

    __shared__ float Ls[Fn * Tn];      // lhs1[f][t]
    __shared__ float Rs[Fn * Tn];      // R2[f][s]
    __shared__ float sig_sh[Tn * Tn];  // sig[s][t]
    __shared__ float VeT[Tn * Tn];     // V_e transposed: VeT[t][u]

    for (int i = tid; i < Fn * Tn; i += 1024) {
        Ls[i] = g_sum[b][i];
        Rs[i] = g_sum[b][Fn * Tn + i];
    }
    {
        int u = tid >> 5, t = tid & 31;
        VeT[t * Tn + u] = V_e[u * Tn + t];
    }
    __syncthreads();

    // product + sigmoid: thread = (t = lane, s = warp)
    {
        const int t = tid & 31;
        const int s = tid >> 5;
        float p = 0.f;
#pragma unroll
        for (int f = 0; f < Fn; f++)
            p = fmaf(Ls[f * Tn + t], Rs[f * Tn + s], p);
        p += b_e[t * Tn + s];
        sig_sh[s * Tn + t] = 1.f / (1.f + expf(-p));
    }
    __syncthreads();

    // E + column softmax over u: thread = (u = lane, s = warp)
    {
        const int u = tid & 31;
        const int s = tid >> 5;
        float e = 0.f;
#pragma unroll
        for (int t = 0; t < Tn; t++)
            e = fmaf(VeT[t * Tn + u], sig_sh[s * Tn + t], e);

        float m = e;
#pragma unroll
        for (int o = 16; o; o >>= 1)
            m = fmaxf(m, __shfl_xor_sync(0xffffffffu, m, o));
        float ex = expf(e - m);
        float ssum = ex;
#pragma unroll
        for (int o = 16; o; o >>= 1)
            ssum += __shfl_xor_sync(0xffffffffu, ssum, o);

        out[b * Tn * Tn + u * Tn + s] = ex / ssum;
    }
}

extern "C" void kernel_launch(void* const* d_in, const int* in_sizes, int n_in,
                              void* d_out, int out_size)
{
    const float* x   = (const float*)d_in[0];
    const float* U1  = (const float*)d_in[1];
    const float* U2  = (const float*)d_in[2];
    const float* U3  = (const float*)d_in[3];
    const float* b_e = (const float*)d_in[4];
    const float* V_e = (const float*)d_in[5];
    float* out = (float*)d_out;

    reduce_kernel<<<NBLK, 256>>>(x, U1, U2, U3);
    sum_partials<<<(Bn * 2 * Fn * Tn) / 256, 256>>>();
    epilogue_kernel<<<Bn, 1024>>>(b_e, V_e, out);
}